// round 1
// baseline (speedup 1.0000x reference)
#include <cuda_runtime.h>

#define BATCH   65536
#define NPLAYER 3
#define OBSD    48
#define NPROP   9
#define NEXT    2
#define EXTOUT  288
#define TB      32
#define THREADS 256

// shared layout (floats)
#define OBS_OFF 0                    // 32*48   = 1536
#define HID_OFF 1536                 // 32*384  = 12288  (ph 288 | eh 64 | oh 32)
#define ENC_OFF (1536+12288)         // 32*576  = 18432
#define H1_OFF  (1536+12288+18432)   // 32*256  = 8192
#define SMEM_FLOATS (1536+12288+18432+8192)

__device__ __forceinline__ float lrelu(float x) { return fmaxf(x, 0.01f * x); }

__global__ __launch_bounds__(THREADS)
void mlpac_kernel(
    const float* __restrict__ obs,
    const float* __restrict__ prop_W1, const float* __restrict__ prop_b1,
    const float* __restrict__ prop_W2, const float* __restrict__ prop_b2,
    const float* __restrict__ ext_W1,  const float* __restrict__ ext_b1,
    const float* __restrict__ ext_W2,  const float* __restrict__ ext_b2,
    const float* __restrict__ opp_W1,  const float* __restrict__ opp_b1,
    const float* __restrict__ opp_W2,  const float* __restrict__ opp_b2,
    const float* __restrict__ pi_W1,   const float* __restrict__ pi_b1,
    const float* __restrict__ pi_W2,   const float* __restrict__ pi_b2,
    const float* __restrict__ pi_W3,   const float* __restrict__ pi_b3,
    float* __restrict__ out)
{
    extern __shared__ float sm[];
    float* s_obs = sm + OBS_OFF;
    float* s_hid = sm + HID_OFF;   // per row: [0:288) prop hidden, [288:352) ext hidden, [352:384) opp hidden
    float* s_enc = sm + ENC_OFF;
    float* s_h1  = sm + H1_OFF;
    float* s_h2  = s_hid;          // reuse hidden region for h2 (freed after stage 1b)

    const int tid = threadIdx.x;
    const int p   = blockIdx.y;
    const int b0  = blockIdx.x * TB;

    // ---------------- stage 0: load obs tile ----------------
    for (int i = tid; i < TB * OBSD; i += THREADS) {
        int r = i / OBSD, k = i % OBSD;
        s_obs[i] = obs[((size_t)(b0 + r) * NPLAYER + p) * OBSD + k];
    }
    __syncthreads();

    // ---------------- stage 1a: branch hidden layers ----------------
    // prop hidden: 32 rows x 9 props x 32
    for (int i = tid; i < TB * NPROP * 32; i += THREADS) {
        int r = i / 288, rest = i % 288, n = rest >> 5, j = rest & 31;
        const float* w = prop_W1 + ((p * NPROP + n) * 2) * 32 + j;
        float h = s_obs[r * OBSD + 2 * n] * w[0]
                + s_obs[r * OBSD + 2 * n + 1] * w[32]
                + prop_b1[(p * NPROP + n) * 32 + j];
        s_hid[r * 384 + n * 32 + j] = lrelu(h);
    }
    // ext hidden: 32 rows x 2 x 32
    for (int i = tid; i < TB * NEXT * 32; i += THREADS) {
        int r = i / 64, rest = i % 64, n = rest >> 5, j = rest & 31;
        const float* w = ext_W1 + ((p * NEXT + n) * 6) * 32 + j;
        float h = ext_b1[(p * NEXT + n) * 32 + j];
        #pragma unroll
        for (int q = 0; q < 6; q++) h += s_obs[r * OBSD + 18 + n * 6 + q] * w[q * 32];
        s_hid[r * 384 + 288 + n * 32 + j] = lrelu(h);
    }
    // opp hidden: 32 rows x 32
    for (int i = tid; i < TB * 32; i += THREADS) {
        int r = i >> 5, j = i & 31;
        const float* w = opp_W1 + (p * 18) * 32 + j;
        float h = opp_b1[p * 32 + j];
        #pragma unroll
        for (int q = 0; q < 18; q++) h += s_obs[r * OBSD + 30 + q] * w[q * 32];
        s_hid[r * 384 + 352 + j] = lrelu(h);
    }
    __syncthreads();

    // ---------------- stage 1b: enc = prop2 + ext2 + opp2 ----------------
    // item = (group g in 0..7, col c in 0..575); rows {g, g+8, g+16, g+24}
    for (int it = tid; it < 8 * 576; it += THREADS) {
        int g = it / 576, c = it % 576;
        int n  = c >> 6,  k  = c & 63;
        int n2 = (c >= EXTOUT) ? 1 : 0, k2 = c - n2 * EXTOUT;
        const float* wp = prop_W2 + ((p * NPROP + n) * 32) * 64 + k;      // stride 64
        const float* we = ext_W2  + ((p * NEXT + n2) * 32) * EXTOUT + k2; // stride 288
        const float* wo = opp_W2  + (p * 32) * 576 + c;                   // stride 576
        int hb0 = (g     ) * 384, hb1 = (g + 8 ) * 384;
        int hb2 = (g + 16) * 384, hb3 = (g + 24) * 384;
        float ap0=0,ap1=0,ap2=0,ap3=0, ae0=0,ae1=0,ae2=0,ae3=0, ao0=0,ao1=0,ao2=0,ao3=0;
        int pb = n * 32, eb = 288 + n2 * 32;
        #pragma unroll 8
        for (int j = 0; j < 32; j++) {
            float wvp = wp[j * 64];
            ap0 += s_hid[hb0 + pb + j] * wvp; ap1 += s_hid[hb1 + pb + j] * wvp;
            ap2 += s_hid[hb2 + pb + j] * wvp; ap3 += s_hid[hb3 + pb + j] * wvp;
            float wve = we[j * EXTOUT];
            ae0 += s_hid[hb0 + eb + j] * wve; ae1 += s_hid[hb1 + eb + j] * wve;
            ae2 += s_hid[hb2 + eb + j] * wve; ae3 += s_hid[hb3 + eb + j] * wve;
            float wvo = wo[j * 576];
            ao0 += s_hid[hb0 + 352 + j] * wvo; ao1 += s_hid[hb1 + 352 + j] * wvo;
            ao2 += s_hid[hb2 + 352 + j] * wvo; ao3 += s_hid[hb3 + 352 + j] * wvo;
        }
        float bp = prop_b2[(p * NPROP + n) * 64 + k];
        float be = ext_b2[(p * NEXT + n2) * EXTOUT + k2];
        float bo = opp_b2[p * 576 + c];
        s_enc[(g     ) * 576 + c] = lrelu(ap0 + bp) + lrelu(ae0 + be) + lrelu(ao0 + bo);
        s_enc[(g + 8 ) * 576 + c] = lrelu(ap1 + bp) + lrelu(ae1 + be) + lrelu(ao1 + bo);
        s_enc[(g + 16) * 576 + c] = lrelu(ap2 + bp) + lrelu(ae2 + be) + lrelu(ao2 + bo);
        s_enc[(g + 24) * 576 + c] = lrelu(ap3 + bp) + lrelu(ae3 + be) + lrelu(ao3 + bo);
    }
    __syncthreads();

    const int warp = tid >> 5, lane = tid & 31;
    const int r0 = warp * 4;

    // ---------------- stage 2: h1 = lrelu(enc @ pi_W1 + b1) ----------------
    {
        const float* W = pi_W1 + (size_t)p * 576 * 256;
        float acc[4][8];
        #pragma unroll
        for (int rr = 0; rr < 4; rr++)
            #pragma unroll
            for (int u = 0; u < 8; u++) acc[rr][u] = 0.f;
        for (int i = 0; i < 576; i += 4) {
            float4 ev[4];
            #pragma unroll
            for (int rr = 0; rr < 4; rr++)
                ev[rr] = *(const float4*)&s_enc[(r0 + rr) * 576 + i];
            #pragma unroll
            for (int ii = 0; ii < 4; ii++) {
                const float* wrow = W + (i + ii) * 256;
                float4 wA = *(const float4*)&wrow[lane * 4];
                float4 wB = *(const float4*)&wrow[128 + lane * 4];
                #pragma unroll
                for (int rr = 0; rr < 4; rr++) {
                    float e = (ii == 0) ? ev[rr].x : (ii == 1) ? ev[rr].y : (ii == 2) ? ev[rr].z : ev[rr].w;
                    acc[rr][0] += e * wA.x; acc[rr][1] += e * wA.y;
                    acc[rr][2] += e * wA.z; acc[rr][3] += e * wA.w;
                    acc[rr][4] += e * wB.x; acc[rr][5] += e * wB.y;
                    acc[rr][6] += e * wB.z; acc[rr][7] += e * wB.w;
                }
            }
        }
        #pragma unroll
        for (int rr = 0; rr < 4; rr++) {
            int cA = lane * 4, cB = 128 + lane * 4;
            #pragma unroll
            for (int u = 0; u < 4; u++) {
                s_h1[(r0 + rr) * 256 + cA + u] = lrelu(acc[rr][u]     + pi_b1[p * 256 + cA + u]);
                s_h1[(r0 + rr) * 256 + cB + u] = lrelu(acc[rr][4 + u] + pi_b1[p * 256 + cB + u]);
            }
        }
    }
    __syncthreads();

    // ---------------- stage 3: h2 = lrelu(h1 @ pi_W2 + b2) ----------------
    {
        const float* W = pi_W2 + (size_t)p * 256 * 256;
        float acc[4][8];
        #pragma unroll
        for (int rr = 0; rr < 4; rr++)
            #pragma unroll
            for (int u = 0; u < 8; u++) acc[rr][u] = 0.f;
        for (int i = 0; i < 256; i += 4) {
            float4 ev[4];
            #pragma unroll
            for (int rr = 0; rr < 4; rr++)
                ev[rr] = *(const float4*)&s_h1[(r0 + rr) * 256 + i];
            #pragma unroll
            for (int ii = 0; ii < 4; ii++) {
                const float* wrow = W + (i + ii) * 256;
                float4 wA = *(const float4*)&wrow[lane * 4];
                float4 wB = *(const float4*)&wrow[128 + lane * 4];
                #pragma unroll
                for (int rr = 0; rr < 4; rr++) {
                    float e = (ii == 0) ? ev[rr].x : (ii == 1) ? ev[rr].y : (ii == 2) ? ev[rr].z : ev[rr].w;
                    acc[rr][0] += e * wA.x; acc[rr][1] += e * wA.y;
                    acc[rr][2] += e * wA.z; acc[rr][3] += e * wA.w;
                    acc[rr][4] += e * wB.x; acc[rr][5] += e * wB.y;
                    acc[rr][6] += e * wB.z; acc[rr][7] += e * wB.w;
                }
            }
        }
        __syncthreads();  // all reads of s_h1 done; s_hid(s_h2) region free
        #pragma unroll
        for (int rr = 0; rr < 4; rr++) {
            int cA = lane * 4, cB = 128 + lane * 4;
            #pragma unroll
            for (int u = 0; u < 4; u++) {
                s_h2[(r0 + rr) * 256 + cA + u] = lrelu(acc[rr][u]     + pi_b2[p * 256 + cA + u]);
                s_h2[(r0 + rr) * 256 + cB + u] = lrelu(acc[rr][4 + u] + pi_b2[p * 256 + cB + u]);
            }
        }
    }
    __syncthreads();

    // ---------------- stage 4: out = tanh(h2 @ pi_W3 + b3) ----------------
    if (tid < TB * 3) {
        int r = tid / 3, a = tid % 3;
        const float* w3 = pi_W3 + (p * 256) * 3 + a;
        float s = pi_b3[p * 3 + a];
        #pragma unroll 8
        for (int i = 0; i < 256; i++) s += s_h2[r * 256 + i] * w3[i * 3];
        out[((size_t)(b0 + r) * NPLAYER + p) * 3 + a] = tanhf(s);
    }
}

extern "C" void kernel_launch(void* const* d_in, const int* in_sizes, int n_in,
                              void* d_out, int out_size)
{
    (void)in_sizes; (void)n_in; (void)out_size;
    const float* obs     = (const float*)d_in[0];
    const float* prop_W1 = (const float*)d_in[1];
    const float* prop_b1 = (const float*)d_in[2];
    const float* prop_W2 = (const float*)d_in[3];
    const float* prop_b2 = (const float*)d_in[4];
    const float* ext_W1  = (const float*)d_in[5];
    const float* ext_b1  = (const float*)d_in[6];
    const float* ext_W2  = (const float*)d_in[7];
    const float* ext_b2  = (const float*)d_in[8];
    const float* opp_W1  = (const float*)d_in[9];
    const float* opp_b1  = (const float*)d_in[10];
    const float* opp_W2  = (const float*)d_in[11];
    const float* opp_b2  = (const float*)d_in[12];
    const float* pi_W1   = (const float*)d_in[13];
    const float* pi_b1   = (const float*)d_in[14];
    const float* pi_W2   = (const float*)d_in[15];
    const float* pi_b2   = (const float*)d_in[16];
    const float* pi_W3   = (const float*)d_in[17];
    const float* pi_b3   = (const float*)d_in[18];
    float* out = (float*)d_out;

    const int smem_bytes = SMEM_FLOATS * sizeof(float);
    cudaFuncSetAttribute(mlpac_kernel, cudaFuncAttributeMaxDynamicSharedMemorySize, smem_bytes);

    dim3 grid(BATCH / TB, NPLAYER);
    mlpac_kernel<<<grid, THREADS, smem_bytes>>>(
        obs, prop_W1, prop_b1, prop_W2, prop_b2,
        ext_W1, ext_b1, ext_W2, ext_b2,
        opp_W1, opp_b1, opp_W2, opp_b2,
        pi_W1, pi_b1, pi_W2, pi_b2, pi_W3, pi_b3, out);
}

// round 2
// speedup vs baseline: 2.5507x; 2.5507x over previous
#include <cuda_runtime.h>

#define BATCH   65536
#define NPLAYER 3
#define OBSD    48
#define NPROP   9
#define NEXT    2
#define EXTOUT  288
#define TB      32
#define THREADS 256

// padded pitches (floats) for conflict-free mma fragment loads
#define PENC 580   // s_enc pitch  (580%32==4 -> (4r+k) all-distinct banks)
#define PH1  260   // s_h1 pitch   (260%32==4)
#define PWB  264   // weight chunk pitch (264%32==8 -> (8k+n) all-distinct banks)
#define KC   16    // k-chunk rows staged per buffer

// shared layout (floats)
#define OBS_OFF 0
#define HID_OFF 1536                         // 32*384
#define ENC_OFF (HID_OFF + 12288)            // 32*580 = 18560
#define H1_OFF  (ENC_OFF + 18560)            // 32*260 = 8320
#define WB_OFF  (H1_OFF + 8320)              // 2*16*264 = 8448
#define SMEM_FLOATS (WB_OFF + 8448)          // 49152 floats = 192KB

__device__ __forceinline__ float lrelu(float x) { return fmaxf(x, 0.01f * x); }

__device__ __forceinline__ unsigned f2tf(float x) {
    unsigned r;
    asm("cvt.rna.tf32.f32 %0, %1;" : "=r"(r) : "f"(x));
    return r;
}

__device__ __forceinline__ void mma_tf32(float d[4], unsigned a0, unsigned a1,
                                         unsigned a2, unsigned a3,
                                         unsigned b0, unsigned b1) {
    asm volatile(
        "mma.sync.aligned.m16n8k8.row.col.f32.tf32.tf32.f32 "
        "{%0,%1,%2,%3}, {%4,%5,%6,%7}, {%8,%9}, {%0,%1,%2,%3};"
        : "+f"(d[0]), "+f"(d[1]), "+f"(d[2]), "+f"(d[3])
        : "r"(a0), "r"(a1), "r"(a2), "r"(a3), "r"(b0), "r"(b1));
}

// Stage one 16-row x 256-col weight chunk: global -> regs
__device__ __forceinline__ void ldg_chunk(float4 r[4], const float* __restrict__ W,
                                          int kc, int tid) {
    #pragma unroll
    for (int q = 0; q < 4; q++) {
        int idx = q * 256 + tid;
        int row = idx >> 6, c4 = idx & 63;
        r[q] = *(const float4*)(W + (size_t)(kc + row) * 256 + c4 * 4);
    }
}
// regs -> smem (tf32-converted), pitch PWB
__device__ __forceinline__ void sts_chunk(const float4 r[4], float* buf, int tid) {
    #pragma unroll
    for (int q = 0; q < 4; q++) {
        int idx = q * 256 + tid;
        int row = idx >> 6, c4 = idx & 63;
        float4 v;
        v.x = __uint_as_float(f2tf(r[q].x));
        v.y = __uint_as_float(f2tf(r[q].y));
        v.z = __uint_as_float(f2tf(r[q].z));
        v.w = __uint_as_float(f2tf(r[q].w));
        *(float4*)(buf + row * PWB + c4 * 4) = v;
    }
}

// One 16-k chunk of mma for a warp tile m32 x n32.
// sA: activation smem (pitch PA), sB: staged weight buffer (pitch PWB).
template<int PA>
__device__ __forceinline__ void mma_chunk(const float* sA, const float* sB,
                                          int kbase, int lane, int n0,
                                          float acc[2][4][4]) {
    const int gr = lane >> 2;    // group row 0..7
    const int gc = lane & 3;     // group col 0..3
    #pragma unroll
    for (int ks = 0; ks < 2; ks++) {
        const int kg = kbase + ks * 8;   // global k of this k8 step (for A)
        const int kl = ks * 8;           // local k within chunk (for B)
        unsigned a[2][4];
        #pragma unroll
        for (int m = 0; m < 2; m++) {
            int r = m * 16 + gr;
            a[m][0] = f2tf(sA[(r    ) * PA + kg + gc    ]);
            a[m][1] = f2tf(sA[(r + 8) * PA + kg + gc    ]);
            a[m][2] = f2tf(sA[(r    ) * PA + kg + gc + 4]);
            a[m][3] = f2tf(sA[(r + 8) * PA + kg + gc + 4]);
        }
        #pragma unroll
        for (int j = 0; j < 4; j++) {
            int n = n0 + j * 8 + gr;
            unsigned b0 = __float_as_uint(sB[(kl + gc    ) * PWB + n]);
            unsigned b1 = __float_as_uint(sB[(kl + gc + 4) * PWB + n]);
            #pragma unroll
            for (int m = 0; m < 2; m++)
                mma_tf32(acc[m][j], a[m][0], a[m][1], a[m][2], a[m][3], b0, b1);
        }
    }
}

// Full GEMM stage: out[32 x 256] = lrelu(A[32 x KTOT] @ W[KTOT x 256] + bias)
template<int KTOT, int PA>
__device__ __forceinline__ void gemm_stage(const float* __restrict__ W,
                                           const float* __restrict__ bias,
                                           const float* sA, float* wbuf,
                                           float* sOut, int outPitch,
                                           int tid) {
    constexpr int NCH = KTOT / KC;
    const int lane = tid & 31;
    const int warp = tid >> 5;
    const int n0 = warp * 32;

    float acc[2][4][4];
    #pragma unroll
    for (int m = 0; m < 2; m++)
        #pragma unroll
        for (int j = 0; j < 4; j++)
            #pragma unroll
            for (int u = 0; u < 4; u++) acc[m][j][u] = 0.f;

    float4 stg[4];
    ldg_chunk(stg, W, 0, tid);
    sts_chunk(stg, wbuf, tid);
    __syncthreads();

    for (int c = 0; c < NCH; c++) {
        if (c + 1 < NCH) ldg_chunk(stg, W, (c + 1) * KC, tid);
        mma_chunk<PA>(sA, wbuf + (c & 1) * (KC * PWB), c * KC, lane, n0, acc);
        __syncthreads();
        if (c + 1 < NCH) {
            sts_chunk(stg, wbuf + ((c + 1) & 1) * (KC * PWB), tid);
            __syncthreads();
        }
    }

    // epilogue
    const int gr = lane >> 2, gc = lane & 3;
    #pragma unroll
    for (int m = 0; m < 2; m++) {
        int r = m * 16 + gr;
        #pragma unroll
        for (int j = 0; j < 4; j++) {
            int cA = n0 + j * 8 + 2 * gc;
            float b0 = bias[cA], b1 = bias[cA + 1];
            sOut[(r    ) * outPitch + cA    ] = lrelu(acc[m][j][0] + b0);
            sOut[(r    ) * outPitch + cA + 1] = lrelu(acc[m][j][1] + b1);
            sOut[(r + 8) * outPitch + cA    ] = lrelu(acc[m][j][2] + b0);
            sOut[(r + 8) * outPitch + cA + 1] = lrelu(acc[m][j][3] + b1);
        }
    }
}

__global__ __launch_bounds__(THREADS)
void mlpac_kernel(
    const float* __restrict__ obs,
    const float* __restrict__ prop_W1, const float* __restrict__ prop_b1,
    const float* __restrict__ prop_W2, const float* __restrict__ prop_b2,
    const float* __restrict__ ext_W1,  const float* __restrict__ ext_b1,
    const float* __restrict__ ext_W2,  const float* __restrict__ ext_b2,
    const float* __restrict__ opp_W1,  const float* __restrict__ opp_b1,
    const float* __restrict__ opp_W2,  const float* __restrict__ opp_b2,
    const float* __restrict__ pi_W1,   const float* __restrict__ pi_b1,
    const float* __restrict__ pi_W2,   const float* __restrict__ pi_b2,
    const float* __restrict__ pi_W3,   const float* __restrict__ pi_b3,
    float* __restrict__ out)
{
    extern __shared__ float sm[];
    float* s_obs = sm + OBS_OFF;
    float* s_hid = sm + HID_OFF;   // row: [0:288) prop | [288:352) ext | [352:384) opp
    float* s_enc = sm + ENC_OFF;   // pitch PENC
    float* s_h1  = sm + H1_OFF;    // pitch PH1
    float* s_wb  = sm + WB_OFF;    // 2 x 16 x PWB
    float* s_h2  = s_hid;          // reuse (pitch 256)

    const int tid = threadIdx.x;
    const int p   = blockIdx.y;
    const int b0  = blockIdx.x * TB;

    // ---------------- stage 0: load obs tile ----------------
    for (int i = tid; i < TB * OBSD; i += THREADS) {
        int r = i / OBSD, k = i % OBSD;
        s_obs[i] = obs[((size_t)(b0 + r) * NPLAYER + p) * OBSD + k];
    }
    __syncthreads();

    // ---------------- stage 1a: branch hidden layers ----------------
    for (int i = tid; i < TB * NPROP * 32; i += THREADS) {
        int r = i / 288, rest = i % 288, n = rest >> 5, j = rest & 31;
        const float* w = prop_W1 + ((p * NPROP + n) * 2) * 32 + j;
        float h = s_obs[r * OBSD + 2 * n] * w[0]
                + s_obs[r * OBSD + 2 * n + 1] * w[32]
                + prop_b1[(p * NPROP + n) * 32 + j];
        s_hid[r * 384 + n * 32 + j] = lrelu(h);
    }
    for (int i = tid; i < TB * NEXT * 32; i += THREADS) {
        int r = i / 64, rest = i % 64, n = rest >> 5, j = rest & 31;
        const float* w = ext_W1 + ((p * NEXT + n) * 6) * 32 + j;
        float h = ext_b1[(p * NEXT + n) * 32 + j];
        #pragma unroll
        for (int q = 0; q < 6; q++) h += s_obs[r * OBSD + 18 + n * 6 + q] * w[q * 32];
        s_hid[r * 384 + 288 + n * 32 + j] = lrelu(h);
    }
    for (int i = tid; i < TB * 32; i += THREADS) {
        int r = i >> 5, j = i & 31;
        const float* w = opp_W1 + (p * 18) * 32 + j;
        float h = opp_b1[p * 32 + j];
        #pragma unroll
        for (int q = 0; q < 18; q++) h += s_obs[r * OBSD + 30 + q] * w[q * 32];
        s_hid[r * 384 + 352 + j] = lrelu(h);
    }
    __syncthreads();

    // ---------------- stage 1b: enc = prop2 + ext2 + opp2 ----------------
    for (int it = tid; it < 8 * 576; it += THREADS) {
        int g = it / 576, c = it % 576;
        int n  = c >> 6,  k  = c & 63;
        int n2 = (c >= EXTOUT) ? 1 : 0, k2 = c - n2 * EXTOUT;
        const float* wp = prop_W2 + ((p * NPROP + n) * 32) * 64 + k;
        const float* we = ext_W2  + ((p * NEXT + n2) * 32) * EXTOUT + k2;
        const float* wo = opp_W2  + (p * 32) * 576 + c;
        int hb0 = (g     ) * 384, hb1 = (g + 8 ) * 384;
        int hb2 = (g + 16) * 384, hb3 = (g + 24) * 384;
        float ap0=0,ap1=0,ap2=0,ap3=0, ae0=0,ae1=0,ae2=0,ae3=0, ao0=0,ao1=0,ao2=0,ao3=0;
        int pb = n * 32, eb = 288 + n2 * 32;
        #pragma unroll 8
        for (int j = 0; j < 32; j++) {
            float wvp = wp[j * 64];
            ap0 += s_hid[hb0 + pb + j] * wvp; ap1 += s_hid[hb1 + pb + j] * wvp;
            ap2 += s_hid[hb2 + pb + j] * wvp; ap3 += s_hid[hb3 + pb + j] * wvp;
            float wve = we[j * EXTOUT];
            ae0 += s_hid[hb0 + eb + j] * wve; ae1 += s_hid[hb1 + eb + j] * wve;
            ae2 += s_hid[hb2 + eb + j] * wve; ae3 += s_hid[hb3 + eb + j] * wve;
            float wvo = wo[j * 576];
            ao0 += s_hid[hb0 + 352 + j] * wvo; ao1 += s_hid[hb1 + 352 + j] * wvo;
            ao2 += s_hid[hb2 + 352 + j] * wvo; ao3 += s_hid[hb3 + 352 + j] * wvo;
        }
        float bp = prop_b2[(p * NPROP + n) * 64 + k];
        float be = ext_b2[(p * NEXT + n2) * EXTOUT + k2];
        float bo = opp_b2[p * 576 + c];
        s_enc[(g     ) * PENC + c] = lrelu(ap0 + bp) + lrelu(ae0 + be) + lrelu(ao0 + bo);
        s_enc[(g + 8 ) * PENC + c] = lrelu(ap1 + bp) + lrelu(ae1 + be) + lrelu(ao1 + bo);
        s_enc[(g + 16) * PENC + c] = lrelu(ap2 + bp) + lrelu(ae2 + be) + lrelu(ao2 + bo);
        s_enc[(g + 24) * PENC + c] = lrelu(ap3 + bp) + lrelu(ae3 + be) + lrelu(ao3 + bo);
    }
    __syncthreads();

    // ---------------- stage 2: h1 = lrelu(enc @ pi_W1 + b1)  [tf32 mma] ----------------
    gemm_stage<576, PENC>(pi_W1 + (size_t)p * 576 * 256, pi_b1 + p * 256,
                          s_enc, s_wb, s_h1, PH1, tid);
    __syncthreads();

    // ---------------- stage 3: h2 = lrelu(h1 @ pi_W2 + b2)  [tf32 mma] ----------------
    gemm_stage<256, PH1>(pi_W2 + (size_t)p * 256 * 256, pi_b2 + p * 256,
                         s_h1, s_wb, s_h2, 256, tid);
    __syncthreads();

    // ---------------- stage 4: out = tanh(h2 @ pi_W3 + b3) ----------------
    if (tid < TB * 3) {
        int r = tid / 3, a = tid % 3;
        const float* w3 = pi_W3 + (p * 256) * 3 + a;
        float s = pi_b3[p * 3 + a];
        #pragma unroll 8
        for (int i = 0; i < 256; i++) s += s_h2[r * 256 + i] * w3[i * 3];
        out[((size_t)(b0 + r) * NPLAYER + p) * 3 + a] = tanhf(s);
    }
}

extern "C" void kernel_launch(void* const* d_in, const int* in_sizes, int n_in,
                              void* d_out, int out_size)
{
    (void)in_sizes; (void)n_in; (void)out_size;
    const float* obs     = (const float*)d_in[0];
    const float* prop_W1 = (const float*)d_in[1];
    const float* prop_b1 = (const float*)d_in[2];
    const float* prop_W2 = (const float*)d_in[3];
    const float* prop_b2 = (const float*)d_in[4];
    const float* ext_W1  = (const float*)d_in[5];
    const float* ext_b1  = (const float*)d_in[6];
    const float* ext_W2  = (const float*)d_in[7];
    const float* ext_b2  = (const float*)d_in[8];
    const float* opp_W1  = (const float*)d_in[9];
    const float* opp_b1  = (const float*)d_in[10];
    const float* opp_W2  = (const float*)d_in[11];
    const float* opp_b2  = (const float*)d_in[12];
    const float* pi_W1   = (const float*)d_in[13];
    const float* pi_b1   = (const float*)d_in[14];
    const float* pi_W2   = (const float*)d_in[15];
    const float* pi_b2   = (const float*)d_in[16];
    const float* pi_W3   = (const float*)d_in[17];
    const float* pi_b3   = (const float*)d_in[18];
    float* out = (float*)d_out;

    const int smem_bytes = SMEM_FLOATS * sizeof(float);
    cudaFuncSetAttribute(mlpac_kernel, cudaFuncAttributeMaxDynamicSharedMemorySize, smem_bytes);

    dim3 grid(BATCH / TB, NPLAYER);
    mlpac_kernel<<<grid, THREADS, smem_bytes>>>(
        obs, prop_W1, prop_b1, prop_W2, prop_b2,
        ext_W1, ext_b1, ext_W2, ext_b2,
        opp_W1, opp_b1, opp_W2, opp_b2,
        pi_W1, pi_b1, pi_W2, pi_b2, pi_W3, pi_b3, out);
}

// round 3
// speedup vs baseline: 3.2551x; 1.2761x over previous
#include <cuda_runtime.h>

#define BATCH   65536
#define NPLAYER 3
#define OBSD    48
#define NPROP   9
#define NEXT    2
#define EXTOUT  288
#define TB      32
#define THREADS 256

// pitches (floats), all verified conflict-free for their access patterns
#define PHID 388   // s_hid: (gr*388+gc)%32 = 4gr+gc -> 32 distinct
#define PENC 580   // s_enc: 580%32==4
#define PH1  260   // s_h1:  260%32==4
#define PWB  264   // pi weight chunks: 264%32==8 -> 8gc+gr distinct
#define PW1B 584   // stage-1b weight matrix: 584%32==8
#define KC   16

// shared layout (floats)
#define HID_OFF 0                          // 32*388 = 12416
#define ENC_OFF 12416                      // 32*580 = 18560
#define H1_OFF  (ENC_OFF + 18560)          // 32*260 = 8320
#define WB_OFF  (H1_OFF + 8320)            // 32*584 = 18688 (also holds obs, pi dbl-buf)
#define SMEM_FLOATS (WB_OFF + 18688)       // 57984 floats = 231936 B

__device__ __forceinline__ float lrelu(float x) { return fmaxf(x, 0.01f * x); }

__device__ __forceinline__ unsigned f2tf(float x) {
    unsigned r;
    asm("cvt.rna.tf32.f32 %0, %1;" : "=r"(r) : "f"(x));
    return r;
}
__device__ __forceinline__ float tf32f(float x) { return __uint_as_float(f2tf(x)); }

__device__ __forceinline__ void mma_tf32(float d[4], unsigned a0, unsigned a1,
                                         unsigned a2, unsigned a3,
                                         unsigned b0, unsigned b1) {
    asm volatile(
        "mma.sync.aligned.m16n8k8.row.col.f32.tf32.tf32.f32 "
        "{%0,%1,%2,%3}, {%4,%5,%6,%7}, {%8,%9}, {%0,%1,%2,%3};"
        : "+f"(d[0]), "+f"(d[1]), "+f"(d[2]), "+f"(d[3])
        : "r"(a0), "r"(a1), "r"(a2), "r"(a3), "r"(b0), "r"(b1));
}

// ---------------- stage-1b pass: enc (+)= lrelu(A_slice @ W + bias) ----------------
// MODE 0: store fp32; MODE 1: accumulate fp32; MODE 2: accumulate + store tf32
template<int HEADCOLS, int NHEADS, int ABASE, int MODE>
__device__ __forceinline__ void enc_pass(const float* __restrict__ W,
                                         const float* __restrict__ bias,
                                         const float* s_hid, float* s_wb,
                                         float* s_enc, int p, int tid) {
    // stage W -> smem as tf32 [k=32][c=576], pitch PW1B
    #pragma unroll 4
    for (int i = 0; i < 72; i++) {
        int idx = i * 256 + tid;
        int k = idx / 576, c = idx - k * 576;
        int head = c / HEADCOLS, cc = c - head * HEADCOLS;
        s_wb[k * PW1B + c] =
            tf32f(W[((size_t)(p * NHEADS + head) * 32 + k) * HEADCOLS + cc]);
    }
    __syncthreads();

    const int lane = tid & 31, warp = tid >> 5;
    const int gr = lane >> 2, gc = lane & 3;
    const int n0 = warp * 72;

    float acc[2][9][4];
    #pragma unroll
    for (int m = 0; m < 2; m++)
        #pragma unroll
        for (int t = 0; t < 9; t++)
            #pragma unroll
            for (int u = 0; u < 4; u++) acc[m][t][u] = 0.f;

    #pragma unroll
    for (int ks = 0; ks < 4; ks++) {
        const int kg = ks * 8;
        int cur = -1;
        unsigned a[2][4];
        #pragma unroll
        for (int t = 0; t < 9; t++) {
            int c0 = n0 + t * 8;
            int head = c0 / HEADCOLS;
            if (head != cur) {
                cur = head;
                int ac = ABASE + head * 32 + kg;
                #pragma unroll
                for (int m = 0; m < 2; m++) {
                    int r = m * 16 + gr;
                    a[m][0] = __float_as_uint(s_hid[(r    ) * PHID + ac + gc    ]);
                    a[m][1] = __float_as_uint(s_hid[(r + 8) * PHID + ac + gc    ]);
                    a[m][2] = __float_as_uint(s_hid[(r    ) * PHID + ac + gc + 4]);
                    a[m][3] = __float_as_uint(s_hid[(r + 8) * PHID + ac + gc + 4]);
                }
            }
            unsigned b0 = __float_as_uint(s_wb[(kg + gc    ) * PW1B + c0 + gr]);
            unsigned b1 = __float_as_uint(s_wb[(kg + gc + 4) * PW1B + c0 + gr]);
            mma_tf32(acc[0][t], a[0][0], a[0][1], a[0][2], a[0][3], b0, b1);
            mma_tf32(acc[1][t], a[1][0], a[1][1], a[1][2], a[1][3], b0, b1);
        }
    }

    // epilogue
    #pragma unroll
    for (int t = 0; t < 9; t++) {
        int cbase = n0 + t * 8 + 2 * gc;
        int head = cbase / HEADCOLS;
        int cc = cbase - head * HEADCOLS;
        float b0 = bias[(p * NHEADS + head) * HEADCOLS + cc];
        float b1 = bias[(p * NHEADS + head) * HEADCOLS + cc + 1];
        #pragma unroll
        for (int m = 0; m < 2; m++) {
            int r = m * 16 + gr;
            float v00 = lrelu(acc[m][t][0] + b0), v01 = lrelu(acc[m][t][1] + b1);
            float v10 = lrelu(acc[m][t][2] + b0), v11 = lrelu(acc[m][t][3] + b1);
            float* e0 = &s_enc[(r    ) * PENC + cbase];
            float* e1 = &s_enc[(r + 8) * PENC + cbase];
            if (MODE == 0) {
                e0[0] = v00; e0[1] = v01; e1[0] = v10; e1[1] = v11;
            } else if (MODE == 1) {
                e0[0] += v00; e0[1] += v01; e1[0] += v10; e1[1] += v11;
            } else {
                e0[0] = tf32f(e0[0] + v00); e0[1] = tf32f(e0[1] + v01);
                e1[0] = tf32f(e1[0] + v10); e1[1] = tf32f(e1[1] + v11);
            }
        }
    }
    __syncthreads();
}

// ---------------- pi-head GEMM (A already tf32 in smem) ----------------
__device__ __forceinline__ void ldg_chunk(float4 r[4], const float* __restrict__ W,
                                          int kc, int tid) {
    #pragma unroll
    for (int q = 0; q < 4; q++) {
        int idx = q * 256 + tid;
        int row = idx >> 6, c4 = idx & 63;
        r[q] = *(const float4*)(W + (size_t)(kc + row) * 256 + c4 * 4);
    }
}
__device__ __forceinline__ void sts_chunk(const float4 r[4], float* buf, int tid) {
    #pragma unroll
    for (int q = 0; q < 4; q++) {
        int idx = q * 256 + tid;
        int row = idx >> 6, c4 = idx & 63;
        float4 v;
        v.x = tf32f(r[q].x); v.y = tf32f(r[q].y);
        v.z = tf32f(r[q].z); v.w = tf32f(r[q].w);
        *(float4*)(buf + row * PWB + c4 * 4) = v;
    }
}

template<int PA>
__device__ __forceinline__ void mma_chunk(const float* sA, const float* sB,
                                          int kbase, int lane, int n0,
                                          float acc[2][4][4]) {
    const int gr = lane >> 2, gc = lane & 3;
    #pragma unroll
    for (int ks = 0; ks < 2; ks++) {
        const int kg = kbase + ks * 8;
        const int kl = ks * 8;
        unsigned a[2][4];
        #pragma unroll
        for (int m = 0; m < 2; m++) {
            int r = m * 16 + gr;
            a[m][0] = __float_as_uint(sA[(r    ) * PA + kg + gc    ]);
            a[m][1] = __float_as_uint(sA[(r + 8) * PA + kg + gc    ]);
            a[m][2] = __float_as_uint(sA[(r    ) * PA + kg + gc + 4]);
            a[m][3] = __float_as_uint(sA[(r + 8) * PA + kg + gc + 4]);
        }
        #pragma unroll
        for (int j = 0; j < 4; j++) {
            int n = n0 + j * 8 + gr;
            unsigned b0 = __float_as_uint(sB[(kl + gc    ) * PWB + n]);
            unsigned b1 = __float_as_uint(sB[(kl + gc + 4) * PWB + n]);
            #pragma unroll
            for (int m = 0; m < 2; m++)
                mma_tf32(acc[m][j], a[m][0], a[m][1], a[m][2], a[m][3], b0, b1);
        }
    }
}

// OUT_TF32: store output activation pre-converted to tf32 (for next mma stage)
template<int KTOT, int PA, bool OUT_TF32>
__device__ __forceinline__ void gemm_stage(const float* __restrict__ W,
                                           const float* __restrict__ bias,
                                           const float* sA, float* wbuf,
                                           float* sOut, int outPitch,
                                           int tid) {
    constexpr int NCH = KTOT / KC;
    const int lane = tid & 31;
    const int warp = tid >> 5;
    const int n0 = warp * 32;

    float acc[2][4][4];
    #pragma unroll
    for (int m = 0; m < 2; m++)
        #pragma unroll
        for (int j = 0; j < 4; j++)
            #pragma unroll
            for (int u = 0; u < 4; u++) acc[m][j][u] = 0.f;

    float4 stg[4];
    ldg_chunk(stg, W, 0, tid);
    sts_chunk(stg, wbuf, tid);
    __syncthreads();

    for (int c = 0; c < NCH; c++) {
        if (c + 1 < NCH) ldg_chunk(stg, W, (c + 1) * KC, tid);
        mma_chunk<PA>(sA, wbuf + (c & 1) * (KC * PWB), c * KC, lane, n0, acc);
        __syncthreads();
        if (c + 1 < NCH) {
            sts_chunk(stg, wbuf + ((c + 1) & 1) * (KC * PWB), tid);
            __syncthreads();
        }
    }

    const int gr = lane >> 2, gc = lane & 3;
    #pragma unroll
    for (int m = 0; m < 2; m++) {
        int r = m * 16 + gr;
        #pragma unroll
        for (int j = 0; j < 4; j++) {
            int cA = n0 + j * 8 + 2 * gc;
            float b0 = bias[cA], b1 = bias[cA + 1];
            float v00 = lrelu(acc[m][j][0] + b0), v01 = lrelu(acc[m][j][1] + b1);
            float v10 = lrelu(acc[m][j][2] + b0), v11 = lrelu(acc[m][j][3] + b1);
            if (OUT_TF32) { v00 = tf32f(v00); v01 = tf32f(v01); v10 = tf32f(v10); v11 = tf32f(v11); }
            sOut[(r    ) * outPitch + cA    ] = v00;
            sOut[(r    ) * outPitch + cA + 1] = v01;
            sOut[(r + 8) * outPitch + cA    ] = v10;
            sOut[(r + 8) * outPitch + cA + 1] = v11;
        }
    }
}

__global__ __launch_bounds__(THREADS)
void mlpac_kernel(
    const float* __restrict__ obs,
    const float* __restrict__ prop_W1, const float* __restrict__ prop_b1,
    const float* __restrict__ prop_W2, const float* __restrict__ prop_b2,
    const float* __restrict__ ext_W1,  const float* __restrict__ ext_b1,
    const float* __restrict__ ext_W2,  const float* __restrict__ ext_b2,
    const float* __restrict__ opp_W1,  const float* __restrict__ opp_b1,
    const float* __restrict__ opp_W2,  const float* __restrict__ opp_b2,
    const float* __restrict__ pi_W1,   const float* __restrict__ pi_b1,
    const float* __restrict__ pi_W2,   const float* __restrict__ pi_b2,
    const float* __restrict__ pi_W3,   const float* __restrict__ pi_b3,
    float* __restrict__ out)
{
    extern __shared__ float sm[];
    float* s_hid = sm + HID_OFF;   // pitch PHID, tf32; row: [0:288) prop | [288:352) ext | [352:384) opp
    float* s_enc = sm + ENC_OFF;   // pitch PENC
    float* s_h1  = sm + H1_OFF;    // pitch PH1, tf32
    float* s_wb  = sm + WB_OFF;    // stage1b W (32xPW1B) / obs / pi dbl-buf
    float* s_obs = s_wb;           // obs staged in wb region (freed before 1b)
    float* s_h2  = s_hid;          // stage3 output reuses hid region (pitch 256, fp32)

    const int tid = threadIdx.x;
    const int p   = blockIdx.y;
    const int b0  = blockIdx.x * TB;

    // ---------------- stage 0: load obs tile ----------------
    for (int i = tid; i < TB * OBSD; i += THREADS) {
        int r = i / OBSD, k = i % OBSD;
        s_obs[i] = obs[((size_t)(b0 + r) * NPLAYER + p) * OBSD + k];
    }
    __syncthreads();

    // ---------------- stage 1a: branch hidden layers (tf32 out) ----------------
    for (int i = tid; i < TB * NPROP * 32; i += THREADS) {
        int r = i / 288, rest = i % 288, n = rest >> 5, j = rest & 31;
        const float* w = prop_W1 + ((p * NPROP + n) * 2) * 32 + j;
        float h = s_obs[r * OBSD + 2 * n] * w[0]
                + s_obs[r * OBSD + 2 * n + 1] * w[32]
                + prop_b1[(p * NPROP + n) * 32 + j];
        s_hid[r * PHID + n * 32 + j] = tf32f(lrelu(h));
    }
    for (int i = tid; i < TB * NEXT * 32; i += THREADS) {
        int r = i / 64, rest = i % 64, n = rest >> 5, j = rest & 31;
        const float* w = ext_W1 + ((p * NEXT + n) * 6) * 32 + j;
        float h = ext_b1[(p * NEXT + n) * 32 + j];
        #pragma unroll
        for (int q = 0; q < 6; q++) h += s_obs[r * OBSD + 18 + n * 6 + q] * w[q * 32];
        s_hid[r * PHID + 288 + n * 32 + j] = tf32f(lrelu(h));
    }
    for (int i = tid; i < TB * 32; i += THREADS) {
        int r = i >> 5, j = i & 31;
        const float* w = opp_W1 + (p * 18) * 32 + j;
        float h = opp_b1[p * 32 + j];
        #pragma unroll
        for (int q = 0; q < 18; q++) h += s_obs[r * OBSD + 30 + q] * w[q * 32];
        s_hid[r * PHID + 352 + j] = tf32f(lrelu(h));
    }
    __syncthreads();   // also: obs region free -> becomes stage1b weight buffer

    // ---------------- stage 1b: enc = lrelu(prop2)+lrelu(ext2)+lrelu(opp2) [mma] ----
    enc_pass<64,     NPROP, 0,   0>(prop_W2, prop_b2, s_hid, s_wb, s_enc, p, tid);
    enc_pass<EXTOUT, NEXT,  288, 1>(ext_W2,  ext_b2,  s_hid, s_wb, s_enc, p, tid);
    enc_pass<576,    1,     352, 2>(opp_W2,  opp_b2,  s_hid, s_wb, s_enc, p, tid);

    // ---------------- stage 2: h1 = lrelu(enc @ pi_W1 + b1) ----------------
    gemm_stage<576, PENC, true>(pi_W1 + (size_t)p * 576 * 256, pi_b1 + p * 256,
                                s_enc, s_wb, s_h1, PH1, tid);
    __syncthreads();

    // ---------------- stage 3: h2 = lrelu(h1 @ pi_W2 + b2) ----------------
    gemm_stage<256, PH1, false>(pi_W2 + (size_t)p * 256 * 256, pi_b2 + p * 256,
                                s_h1, s_wb, s_h2, 256, tid);
    __syncthreads();

    // ---------------- stage 4: out = tanh(h2 @ pi_W3 + b3) ----------------
    if (tid < TB * 3) {
        int r = tid / 3, a = tid % 3;
        const float* w3 = pi_W3 + (p * 256) * 3 + a;
        float s = pi_b3[p * 3 + a];
        #pragma unroll 8
        for (int i = 0; i < 256; i++) s += s_h2[r * 256 + i] * w3[i * 3];
        out[((size_t)(b0 + r) * NPLAYER + p) * 3 + a] = tanhf(s);
    }
}

extern "C" void kernel_launch(void* const* d_in, const int* in_sizes, int n_in,
                              void* d_out, int out_size)
{
    (void)in_sizes; (void)n_in; (void)out_size;
    const float* obs     = (const float*)d_in[0];
    const float* prop_W1 = (const float*)d_in[1];
    const float* prop_b1 = (const float*)d_in[2];
    const float* prop_W2 = (const float*)d_in[3];
    const float* prop_b2 = (const float*)d_in[4];
    const float* ext_W1  = (const float*)d_in[5];
    const float* ext_b1  = (const float*)d_in[6];
    const float* ext_W2  = (const float*)d_in[7];
    const float* ext_b2  = (const float*)d_in[8];
    const float* opp_W1  = (const float*)d_in[9];
    const float* opp_b1  = (const float*)d_in[10];
    const float* opp_W2  = (const float*)d_in[11];
    const float* opp_b2  = (const float*)d_in[12];
    const float* pi_W1   = (const float*)d_in[13];
    const float* pi_b1   = (const float*)d_in[14];
    const float* pi_W2   = (const float*)d_in[15];
    const float* pi_b2   = (const float*)d_in[16];
    const float* pi_W3   = (const float*)d_in[17];
    const float* pi_b3   = (const float*)d_in[18];
    float* out = (float*)d_out;

    const int smem_bytes = SMEM_FLOATS * sizeof(float);
    cudaFuncSetAttribute(mlpac_kernel, cudaFuncAttributeMaxDynamicSharedMemorySize, smem_bytes);

    dim3 grid(BATCH / TB, NPLAYER);
    mlpac_kernel<<<grid, THREADS, smem_bytes>>>(
        obs, prop_W1, prop_b1, prop_W2, prop_b2,
        ext_W1, ext_b1, ext_W2, ext_b2,
        opp_W1, opp_b1, opp_W2, opp_b2,
        pi_W1, pi_b1, pi_W2, pi_b2, pi_W3, pi_b3, out);
}